// round 4
// baseline (speedup 1.0000x reference)
#include <cuda_runtime.h>
#include <cuda_bf16.h>
#include <math.h>
#include <stdint.h>

// ---------------------------------------------------------------------------
// Problem constants (fixed by setup_inputs)
// ---------------------------------------------------------------------------
#define HDIM 2048
#define NEXP 16
#define TOPK 4
#define IDIM 1408
#define ISDIM 5632
#define TMAX 8192

// ---------------------------------------------------------------------------
// Device scratch (no allocations allowed anywhere)
//   T*Is == T*K*I == 46,137,344 floats (184.5 MB each) -> reuse between
//   shared-expert phase and routed phase (kernels are stream-ordered).
// ---------------------------------------------------------------------------
#define SCRATCH_ELEMS 46137344
__device__ float g_scratchG[SCRATCH_ELEMS];
__device__ float g_scratchH[SCRATCH_ELEMS];
__device__ int   g_topi[TMAX * TOPK];
__device__ float g_topw[TMAX * TOPK];
__device__ float g_gate[TMAX];
__device__ int   g_counts[NEXP];
__device__ int   g_offsets[NEXP];
__device__ int   g_cursor[NEXP];
__device__ int   g_btok[TMAX * TOPK];
__device__ float g_bw[TMAX * TOPK];

// ---------------------------------------------------------------------------
// f32x2 packed-FMA helpers (Blackwell FFMA2 path, 2 FMA/lane/instr)
// ---------------------------------------------------------------------------
__device__ __forceinline__ unsigned long long pk2(float lo, float hi) {
    unsigned long long r;
    asm("mov.b64 %0, {%1, %2};" : "=l"(r) : "f"(lo), "f"(hi));
    return r;
}
__device__ __forceinline__ unsigned long long fma2(unsigned long long a,
                                                   unsigned long long b,
                                                   unsigned long long c) {
    unsigned long long d;
    asm("fma.rn.f32x2 %0, %1, %2, %3;" : "=l"(d) : "l"(a), "l"(b), "l"(c));
    return d;
}
__device__ __forceinline__ float2 upk2(unsigned long long v) {
    float2 r;
    asm("mov.b64 {%0, %1}, %2;" : "=f"(r.x), "=f"(r.y) : "l"(v));
    return r;
}

// ---------------------------------------------------------------------------
// Router: logits = x @ gate_w  (16), sg = x @ sg_w (1)
//   softmax -> top-4 (no renorm), sigmoid gate; per-expert counts via atomics
//   One block (256 threads) per token.
// ---------------------------------------------------------------------------
__global__ void router_k(const float* __restrict__ x,
                         const float* __restrict__ gw,
                         const float* __restrict__ sgw,
                         int* __restrict__ topi, float* __restrict__ topw,
                         float* __restrict__ gatev, int* __restrict__ counts) {
    int t = blockIdx.x;
    const float* xr = x + (size_t)t * HDIM;

    float acc[17];
#pragma unroll
    for (int e = 0; e < 17; e++) acc[e] = 0.f;

    for (int h = threadIdx.x; h < HDIM; h += blockDim.x) {
        float xv = xr[h];
        const float* g = gw + h * NEXP;
#pragma unroll
        for (int e = 0; e < NEXP; e++) acc[e] += xv * g[e];
        acc[16] += xv * sgw[h];
    }

    __shared__ float red[17][8];
    int lane = threadIdx.x & 31, w = threadIdx.x >> 5;
#pragma unroll
    for (int e = 0; e < 17; e++) {
        float v = acc[e];
#pragma unroll
        for (int o = 16; o; o >>= 1) v += __shfl_down_sync(0xffffffffu, v, o);
        if (lane == 0) red[e][w] = v;
    }
    __syncthreads();

    if (threadIdx.x == 0) {
        float l[17];
#pragma unroll
        for (int e = 0; e < 17; e++) {
            float s = 0.f;
#pragma unroll
            for (int i = 0; i < 8; i++) s += red[e][i];
            l[e] = s;
        }
        // softmax over experts
        float mx = l[0];
#pragma unroll
        for (int e = 1; e < NEXP; e++) mx = fmaxf(mx, l[e]);
        float p[NEXP], sum = 0.f;
#pragma unroll
        for (int e = 0; e < NEXP; e++) { p[e] = expf(l[e] - mx); sum += p[e]; }
        float inv = 1.f / sum;
        // top-4 (strict >, keeps lowest index on ties like jax top_k)
        bool used[NEXP];
#pragma unroll
        for (int e = 0; e < NEXP; e++) used[e] = false;
        for (int k = 0; k < TOPK; k++) {
            int best = 0; float bv = -1.f;
#pragma unroll
            for (int e = 0; e < NEXP; e++)
                if (!used[e] && p[e] > bv) { bv = p[e]; best = e; }
            used[best] = true;
            topi[t * TOPK + k] = best;
            topw[t * TOPK + k] = bv * inv;
            atomicAdd(&counts[best], 1);
        }
        gatev[t] = 1.f / (1.f + expf(-l[16]));
    }
}

__global__ void zero_counts_k(int* __restrict__ counts) {
    if (threadIdx.x < NEXP) counts[threadIdx.x] = 0;
}

__global__ void prefix_k(const int* __restrict__ counts,
                         int* __restrict__ offsets, int* __restrict__ cursor) {
    if (threadIdx.x == 0) {
        int s = 0;
        for (int e = 0; e < NEXP; e++) {
            offsets[e] = s; cursor[e] = s; s += counts[e];
        }
    }
}

__global__ void scatter_k(const int* __restrict__ topi,
                          const float* __restrict__ topw,
                          int* __restrict__ cursor,
                          int* __restrict__ btok, float* __restrict__ bw,
                          int TK) {
    int i = blockIdx.x * blockDim.x + threadIdx.x;
    if (i < TK) {
        int e = topi[i];
        int pos = atomicAdd(&cursor[e], 1);
        btok[pos] = i >> 2;   // token id
        bw[pos] = topw[i];
    }
}

// ---------------------------------------------------------------------------
// Tiled SGEMM, 128x128 tile, BK=16, 256 threads, 8x8 per thread, f32x2 FMAs.
//   MODE 0 (STORE):      C[(off+m)*N+n] = acc
//   MODE 1 (SILUMUL):    C[idx] = silu(G[idx]) * acc
//   MODE 2 (SCALESTORE): C[m*N+n] = rowscale[m] * acc       (dense out write)
//   MODE 3 (SCATTER):    atomicAdd(&C[tok*N+n], w * acc)    (routed combine)
// ROUTED: blockIdx.z = expert; rows bounded by counts[e]; B += e*Kd*N;
//         A-rows gathered through btok (MODE 0/1) or compact (MODE 3).
// ---------------------------------------------------------------------------
#define M_STORE 0
#define M_SILUMUL 1
#define M_SCALESTORE 2
#define M_SCATTER 3

#define BM 128
#define BN 128
#define BKT 16

template <int MODE, bool ROUTED>
__global__ void __launch_bounds__(256, 2)
gemm_k(const float* __restrict__ A, const float* __restrict__ Bmat,
       float* __restrict__ C, const float* __restrict__ Gbuf,
       const float* __restrict__ rowscale,
       const int* __restrict__ counts, const int* __restrict__ offsets,
       const int* __restrict__ btok, const float* __restrict__ bw,
       int M, int N, int Kd) {
    __shared__ float As[BKT][BM + 4];
    __shared__ float Bs[BKT][BN];

    int off = 0;
    int Ne = M;
    const float* B = Bmat;
    if (ROUTED) {
        int e = blockIdx.z;
        Ne = counts[e];
        off = offsets[e];
        B = Bmat + (size_t)e * Kd * N;
    }
    int rowblock = blockIdx.y * BM;
    if (rowblock >= Ne) return;        // uniform per block -> safe early exit
    int colblock = blockIdx.x * BN;

    int tid = threadIdx.x;

    // A-tile loader: thread loads float4 at (row = ar0 + 64*i, k = ak)
    int ak = (tid & 3) * 4;
    int ar0 = tid >> 2;
    const float* aptr[2];
#pragma unroll
    for (int i = 0; i < 2; i++) {
        int r = ar0 + 64 * i;
        int m = rowblock + r;
        const float* p = nullptr;
        if (m < Ne) {
            if (ROUTED) {
                if (MODE == M_SCATTER) {
                    p = A + (size_t)(off + m) * Kd;        // compact rows
                } else {
                    int tok = btok[off + m];               // gathered rows
                    p = A + (size_t)tok * Kd;
                }
            } else {
                p = A + (size_t)m * Kd;
            }
        }
        aptr[i] = p;
    }
    // B-tile loader: thread loads float4 at (row = br0 + 8*i, col = bc)
    int br0 = tid >> 5;
    int bc = (tid & 31) * 4;

    // Per-thread output: rows tm..tm+7, cols {colA..+3, colA+64..+67}
    int tm = (tid >> 4) * 8;
    int colA = (tid & 15) * 4;

    unsigned long long acc[8][4];
#pragma unroll
    for (int i = 0; i < 8; i++)
#pragma unroll
        for (int j = 0; j < 4; j++) acc[i][j] = 0ull;

    for (int k0 = 0; k0 < Kd; k0 += BKT) {
#pragma unroll
        for (int i = 0; i < 2; i++) {
            float4 v = make_float4(0.f, 0.f, 0.f, 0.f);
            if (aptr[i]) v = *reinterpret_cast<const float4*>(aptr[i] + k0 + ak);
            int r = ar0 + 64 * i;
            As[ak + 0][r] = v.x;
            As[ak + 1][r] = v.y;
            As[ak + 2][r] = v.z;
            As[ak + 3][r] = v.w;
        }
#pragma unroll
        for (int i = 0; i < 2; i++) {
            int r = br0 + 8 * i;
            float4 v = *reinterpret_cast<const float4*>(
                B + (size_t)(k0 + r) * N + colblock + bc);
            *reinterpret_cast<float4*>(&Bs[r][bc]) = v;
        }
        __syncthreads();

#pragma unroll
        for (int kk = 0; kk < BKT; kk++) {
            float4 a0 = *reinterpret_cast<const float4*>(&As[kk][tm]);
            float4 a1 = *reinterpret_cast<const float4*>(&As[kk][tm + 4]);
            float4 bA = *reinterpret_cast<const float4*>(&Bs[kk][colA]);
            float4 bB = *reinterpret_cast<const float4*>(&Bs[kk][colA + 64]);
            unsigned long long b2[4];
            b2[0] = pk2(bA.x, bA.y);
            b2[1] = pk2(bA.z, bA.w);
            b2[2] = pk2(bB.x, bB.y);
            b2[3] = pk2(bB.z, bB.w);
            float a[8] = {a0.x, a0.y, a0.z, a0.w, a1.x, a1.y, a1.z, a1.w};
#pragma unroll
            for (int i = 0; i < 8; i++) {
                unsigned long long a2 = pk2(a[i], a[i]);
#pragma unroll
                for (int j = 0; j < 4; j++) acc[i][j] = fma2(a2, b2[j], acc[i][j]);
            }
        }
        __syncthreads();
    }

    // Epilogue
#pragma unroll
    for (int i = 0; i < 8; i++) {
        int m = rowblock + tm + i;
        if (m >= Ne) break;
        float scale = 1.f;
        int tok = 0;
        if (MODE == M_SCATTER) {
            tok = btok[off + m];
            scale = bw[off + m];
        } else if (MODE == M_SCALESTORE) {
            scale = rowscale[m];
        }
#pragma unroll
        for (int j = 0; j < 4; j++) {
            float2 v = upk2(acc[i][j]);
            int n = colblock + ((j < 2) ? (colA + 2 * j) : (colA + 64 + 2 * (j - 2)));
            if (MODE == M_STORE) {
                size_t idx = (size_t)(off + m) * N + n;
                *reinterpret_cast<float2*>(&C[idx]) = v;
            } else if (MODE == M_SILUMUL) {
                size_t idx = (size_t)(off + m) * N + n;
                float2 g = *reinterpret_cast<const float2*>(&Gbuf[idx]);
                float2 o;
                o.x = (g.x / (1.f + expf(-g.x))) * v.x;
                o.y = (g.y / (1.f + expf(-g.y))) * v.y;
                *reinterpret_cast<float2*>(&C[idx]) = o;
            } else if (MODE == M_SCALESTORE) {
                size_t idx = (size_t)m * N + n;
                float2 o = make_float2(scale * v.x, scale * v.y);
                *reinterpret_cast<float2*>(&C[idx]) = o;
            } else {  // M_SCATTER
                size_t idx = (size_t)tok * N + n;
                atomicAdd(&C[idx], scale * v.x);
                atomicAdd(&C[idx + 1], scale * v.y);
            }
        }
    }
}

// ---------------------------------------------------------------------------
// kernel_launch
// ---------------------------------------------------------------------------
extern "C" void kernel_launch(void* const* d_in, const int* in_sizes, int n_in,
                              void* d_out, int out_size) {
    const float* x   = (const float*)d_in[0];  // [T, H]
    const float* gw  = (const float*)d_in[1];  // [H, E]
    const float* w1  = (const float*)d_in[2];  // [E, H, I]
    const float* w3  = (const float*)d_in[3];  // [E, H, I]
    const float* w2  = (const float*)d_in[4];  // [E, I, H]
    const float* sw1 = (const float*)d_in[5];  // [H, Is]
    const float* sw3 = (const float*)d_in[6];  // [H, Is]
    const float* sw2 = (const float*)d_in[7];  // [Is, H]
    const float* sgw = (const float*)d_in[8];  // [H, 1]
    float* out = (float*)d_out;

    const int T = in_sizes[0] / HDIM;  // 8192
    const int TK = T * TOPK;

    // resolve device-global scratch addresses (host API, not a stream op)
    float *sG, *sH, *topw, *bw, *gatev;
    int *topi, *counts, *offsets, *cursor, *btok;
    cudaGetSymbolAddress((void**)&sG, g_scratchG);
    cudaGetSymbolAddress((void**)&sH, g_scratchH);
    cudaGetSymbolAddress((void**)&topi, g_topi);
    cudaGetSymbolAddress((void**)&topw, g_topw);
    cudaGetSymbolAddress((void**)&gatev, g_gate);
    cudaGetSymbolAddress((void**)&counts, g_counts);
    cudaGetSymbolAddress((void**)&offsets, g_offsets);
    cudaGetSymbolAddress((void**)&cursor, g_cursor);
    cudaGetSymbolAddress((void**)&btok, g_btok);
    cudaGetSymbolAddress((void**)&bw, g_bw);

    // ---- routing ----
    zero_counts_k<<<1, 32>>>(counts);
    router_k<<<T, 256>>>(x, gw, sgw, topi, topw, gatev, counts);
    prefix_k<<<1, 32>>>(counts, offsets, cursor);
    scatter_k<<<(TK + 255) / 256, 256>>>(topi, topw, cursor, btok, bw, TK);

    // ---- shared expert: out = sigmoid(x@sg_w) * ((silu(x@sw1) * (x@sw3)) @ sw2)
    {
        dim3 grid1(ISDIM / BN, T / BM);
        gemm_k<M_STORE, false><<<grid1, 256>>>(
            x, sw1, sG, nullptr, nullptr, nullptr, nullptr, nullptr, nullptr,
            T, ISDIM, HDIM);
        gemm_k<M_SILUMUL, false><<<grid1, 256>>>(
            x, sw3, sH, sG, nullptr, nullptr, nullptr, nullptr, nullptr,
            T, ISDIM, HDIM);
        dim3 grid2(HDIM / BN, T / BM);
        gemm_k<M_SCALESTORE, false><<<grid2, 256>>>(
            sH, sw2, out, nullptr, gatev, nullptr, nullptr, nullptr, nullptr,
            T, HDIM, ISDIM);   // writes ALL of d_out (covers 0xAA poison)
    }

    // ---- routed experts (token-grouped, sparse) ----
    {
        dim3 grid1(IDIM / BN, T / BM, NEXP);
        gemm_k<M_STORE, true><<<grid1, 256>>>(
            x, w1, sG, nullptr, nullptr, counts, offsets, btok, bw,
            T, IDIM, HDIM);
        gemm_k<M_SILUMUL, true><<<grid1, 256>>>(
            x, w3, sH, sG, nullptr, counts, offsets, btok, bw,
            T, IDIM, HDIM);
        dim3 grid2(HDIM / BN, T / BM, NEXP);
        gemm_k<M_SCATTER, true><<<grid2, 256>>>(
            sH, w2, out, nullptr, nullptr, counts, offsets, btok, bw,
            T, HDIM, IDIM);
    }
}